// round 1
// baseline (speedup 1.0000x reference)
#include <cuda_runtime.h>
#include <cuda_bf16.h>

#define T_TOK 1024
#define HDIM  2048
#define NEXP  64
#define IDIM  768
#define TOPK  8
#define MAXPOS (T_TOK * TOPK)

#define BM 64
#define BN 64
#define BK 16

// ---------------- scratch (static device allocations; no cudaMalloc) ----------------
__device__ float d_topk_w[MAXPOS];
__device__ int   d_topk_idx[MAXPOS];
__device__ int   d_counts[NEXP];
__device__ int   d_offsets[NEXP];
__device__ int   d_cursor[NEXP];
__device__ int   d_perm[MAXPOS];     // position -> token id
__device__ int   d_posmap[MAXPOS];   // (t*TOPK+k) -> position
__device__ float d_act[(size_t)MAXPOS * IDIM];   // 25 MB: silu(gate)*up per (tok,expert)
__device__ float d_part[(size_t)MAXPOS * HDIM];  // 67 MB: down output per (tok,expert)

// ---------------- kernel 0: zero counters ----------------
__global__ void zero_counts_kernel() {
    if (threadIdx.x < NEXP) d_counts[threadIdx.x] = 0;
}

// ---------------- kernel 1: router (logits -> top8 -> renormalized weights) ----------
// One block per token, 256 threads. softmax+topk+renorm == softmax over top-8 logits.
__global__ __launch_bounds__(256) void router_kernel(
    const float* __restrict__ x, const float* __restrict__ rw)
{
    __shared__ float xs[HDIM];
    __shared__ float logits[NEXP];
    const int t = blockIdx.x;
    const float* xrow = x + (size_t)t * HDIM;
    for (int j = threadIdx.x; j < HDIM; j += blockDim.x) xs[j] = xrow[j];
    __syncthreads();

    const int warp = threadIdx.x >> 5;
    const int lane = threadIdx.x & 31;
    for (int e = warp; e < NEXP; e += 8) {
        const float* w = rw + (size_t)e * HDIM;
        float s = 0.f;
        for (int j = lane; j < HDIM; j += 32) s = fmaf(xs[j], w[j], s);
        #pragma unroll
        for (int o = 16; o > 0; o >>= 1) s += __shfl_xor_sync(0xffffffffu, s, o);
        if (lane == 0) logits[e] = s;
    }
    __syncthreads();

    if (threadIdx.x == 0) {
        float vals[TOPK]; int idx[TOPK];
        bool used[NEXP];
        #pragma unroll
        for (int e = 0; e < NEXP; e++) used[e] = false;
        for (int k = 0; k < TOPK; k++) {
            float best = -1e30f; int bi = 0;
            for (int e = 0; e < NEXP; e++)
                if (!used[e] && logits[e] > best) { best = logits[e]; bi = e; }
            used[bi] = true; vals[k] = best; idx[k] = bi;
        }
        const float mx = vals[0];
        float sum = 0.f;
        #pragma unroll
        for (int k = 0; k < TOPK; k++) { vals[k] = expf(vals[k] - mx); sum += vals[k]; }
        const float inv = 1.f / sum;
        #pragma unroll
        for (int k = 0; k < TOPK; k++) {
            d_topk_w[t * TOPK + k]   = vals[k] * inv;
            d_topk_idx[t * TOPK + k] = idx[k];
            atomicAdd(&d_counts[idx[k]], 1);
        }
    }
}

// ---------------- kernel 2: exclusive scan (tiny, 1 thread) ----------------
__global__ void scan_kernel() {
    int off = 0;
    for (int e = 0; e < NEXP; e++) {
        d_offsets[e] = off; d_cursor[e] = off; off += d_counts[e];
    }
}

// ---------------- kernel 3: build per-expert token lists ----------------
__global__ void fill_kernel() {
    const int i = blockIdx.x * blockDim.x + threadIdx.x;
    if (i < MAXPOS) {
        const int e = d_topk_idx[i];
        const int pos = atomicAdd(&d_cursor[e], 1);
        d_perm[pos] = i / TOPK;
        d_posmap[i] = pos;
    }
}

// ---------------- kernel 4: fused gate/up GEMM + SiLU ----------------
// C[M=tokens_of_e, N=I] with K=H. A gathered via d_perm; Bg/Bu from expert weights.
// grid = (NEXP, IDIM/BN, T_TOK/BM), block = 256.
__global__ __launch_bounds__(256) void gemm1_kernel(
    const float* __restrict__ x,
    const float* __restrict__ gw,
    const float* __restrict__ uw)
{
    const int e = blockIdx.x;
    const int cnt = d_counts[e];
    const int m0 = blockIdx.z * BM;
    if (m0 >= cnt) return;
    const int n0 = blockIdx.y * BN;
    const int off = d_offsets[e];

    __shared__ float As[BK][BM];
    __shared__ float Bg[BK][BN];
    __shared__ float Bu[BK][BN];

    const int tid  = threadIdx.x;
    const int lrow = tid >> 2;          // 0..63
    const int lk4  = (tid & 3) * 4;     // 0,4,8,12

    const int amrow = m0 + lrow;
    const float* arow = (amrow < cnt) ? (x + (size_t)d_perm[off + amrow] * HDIM) : nullptr;
    const float* grow = gw + ((size_t)e * IDIM + (n0 + lrow)) * HDIM;
    const float* urow = uw + ((size_t)e * IDIM + (n0 + lrow)) * HDIM;

    const int tx = tid & 15, ty = tid >> 4;
    float accg[4][4] = {}, accu[4][4] = {};

    for (int k0 = 0; k0 < HDIM; k0 += BK) {
        const float4 av = arow ? *(const float4*)(arow + k0 + lk4) : make_float4(0.f,0.f,0.f,0.f);
        const float4 gv = *(const float4*)(grow + k0 + lk4);
        const float4 uv = *(const float4*)(urow + k0 + lk4);
        __syncthreads();   // previous iteration's compute done before overwrite
        As[lk4+0][lrow]=av.x; As[lk4+1][lrow]=av.y; As[lk4+2][lrow]=av.z; As[lk4+3][lrow]=av.w;
        Bg[lk4+0][lrow]=gv.x; Bg[lk4+1][lrow]=gv.y; Bg[lk4+2][lrow]=gv.z; Bg[lk4+3][lrow]=gv.w;
        Bu[lk4+0][lrow]=uv.x; Bu[lk4+1][lrow]=uv.y; Bu[lk4+2][lrow]=uv.z; Bu[lk4+3][lrow]=uv.w;
        __syncthreads();
        #pragma unroll
        for (int kk = 0; kk < BK; kk++) {
            const float4 a  = *(const float4*)&As[kk][ty * 4];
            const float4 bg = *(const float4*)&Bg[kk][tx * 4];
            const float4 bu = *(const float4*)&Bu[kk][tx * 4];
            const float avr[4] = {a.x, a.y, a.z, a.w};
            const float bgr[4] = {bg.x, bg.y, bg.z, bg.w};
            const float bur[4] = {bu.x, bu.y, bu.z, bu.w};
            #pragma unroll
            for (int i = 0; i < 4; i++)
                #pragma unroll
                for (int j = 0; j < 4; j++) {
                    accg[i][j] = fmaf(avr[i], bgr[j], accg[i][j]);
                    accu[i][j] = fmaf(avr[i], bur[j], accu[i][j]);
                }
        }
    }

    #pragma unroll
    for (int i = 0; i < 4; i++) {
        const int m = m0 + ty * 4 + i;
        if (m >= cnt) continue;
        float* orow = d_act + (size_t)(off + m) * IDIM + n0 + tx * 4;
        #pragma unroll
        for (int j = 0; j < 4; j++) {
            const float g = accg[i][j];
            const float s = g / (1.f + expf(-g));   // SiLU
            orow[j] = s * accu[i][j];
        }
    }
}

// ---------------- kernel 5: down GEMM ----------------
// C[M=tokens_of_e, N=H] with K=I. A = d_act (contiguous rows), B = down_w[e].
// grid = (NEXP, HDIM/BN, T_TOK/BM), block = 256.
__global__ __launch_bounds__(256) void gemm2_kernel(const float* __restrict__ dw)
{
    const int e = blockIdx.x;
    const int cnt = d_counts[e];
    const int m0 = blockIdx.z * BM;
    if (m0 >= cnt) return;
    const int n0 = blockIdx.y * BN;
    const int off = d_offsets[e];

    __shared__ float As[BK][BM];
    __shared__ float Bs[BK][BN];

    const int tid  = threadIdx.x;
    const int lrow = tid >> 2;
    const int lk4  = (tid & 3) * 4;

    const int amrow = m0 + lrow;
    const float* arow = (amrow < cnt) ? (d_act + (size_t)(off + amrow) * IDIM) : nullptr;
    const float* brow = dw + ((size_t)e * HDIM + (n0 + lrow)) * IDIM;

    const int tx = tid & 15, ty = tid >> 4;
    float acc[4][4] = {};

    for (int k0 = 0; k0 < IDIM; k0 += BK) {
        const float4 av = arow ? *(const float4*)(arow + k0 + lk4) : make_float4(0.f,0.f,0.f,0.f);
        const float4 bv = *(const float4*)(brow + k0 + lk4);
        __syncthreads();
        As[lk4+0][lrow]=av.x; As[lk4+1][lrow]=av.y; As[lk4+2][lrow]=av.z; As[lk4+3][lrow]=av.w;
        Bs[lk4+0][lrow]=bv.x; Bs[lk4+1][lrow]=bv.y; Bs[lk4+2][lrow]=bv.z; Bs[lk4+3][lrow]=bv.w;
        __syncthreads();
        #pragma unroll
        for (int kk = 0; kk < BK; kk++) {
            const float4 a = *(const float4*)&As[kk][ty * 4];
            const float4 b = *(const float4*)&Bs[kk][tx * 4];
            const float avr[4] = {a.x, a.y, a.z, a.w};
            const float bvr[4] = {b.x, b.y, b.z, b.w};
            #pragma unroll
            for (int i = 0; i < 4; i++)
                #pragma unroll
                for (int j = 0; j < 4; j++)
                    acc[i][j] = fmaf(avr[i], bvr[j], acc[i][j]);
        }
    }

    #pragma unroll
    for (int i = 0; i < 4; i++) {
        const int m = m0 + ty * 4 + i;
        if (m >= cnt) continue;
        float* orow = d_part + (size_t)(off + m) * HDIM + n0 + tx * 4;
        #pragma unroll
        for (int j = 0; j < 4; j++) orow[j] = acc[i][j];
    }
}

// ---------------- kernel 6: deterministic weighted combine ----------------
// out[t][h] = sum_k w[t][k] * part[posmap[t][k]][h]
__global__ __launch_bounds__(256) void combine_kernel(float* __restrict__ out)
{
    const int t = blockIdx.x;
    const int h = blockIdx.y * 256 + threadIdx.x;
    float w[TOPK]; int pos[TOPK];
    #pragma unroll
    for (int k = 0; k < TOPK; k++) {
        w[k]   = d_topk_w[t * TOPK + k];
        pos[k] = d_posmap[t * TOPK + k];
    }
    float s = 0.f;
    #pragma unroll
    for (int k = 0; k < TOPK; k++)
        s = fmaf(w[k], d_part[(size_t)pos[k] * HDIM + h], s);
    out[(size_t)t * HDIM + h] = s;
}

// ---------------- launch ----------------
extern "C" void kernel_launch(void* const* d_in, const int* in_sizes, int n_in,
                              void* d_out, int out_size)
{
    const float* x  = (const float*)d_in[0];  // [1,1024,2048]
    const float* rw = (const float*)d_in[1];  // [64,2048]
    const float* gw = (const float*)d_in[2];  // [64,768,2048]
    const float* uw = (const float*)d_in[3];  // [64,768,2048]
    const float* dw = (const float*)d_in[4];  // [64,2048,768]
    float* out = (float*)d_out;

    zero_counts_kernel<<<1, 64>>>();
    router_kernel<<<T_TOK, 256>>>(x, rw);
    scan_kernel<<<1, 1>>>();
    fill_kernel<<<MAXPOS / 256, 256>>>();
    gemm1_kernel<<<dim3(NEXP, IDIM / BN, T_TOK / BM), 256>>>(x, gw, uw);
    gemm2_kernel<<<dim3(NEXP, HDIM / BN, T_TOK / BM), 256>>>(dw);
    combine_kernel<<<dim3(T_TOK, HDIM / 256), 256>>>(out);
}

// round 2
// speedup vs baseline: 2.7977x; 2.7977x over previous
#include <cuda_runtime.h>
#include <cuda_bf16.h>
#include <cstdint>

#define T_TOK 1024
#define HDIM  2048
#define NEXP  64
#define IDIM  768
#define TOPK  8
#define MAXPOS (T_TOK * TOPK)

#define BM 128
#define BN 64
#define BK 16
#define SA 20            // padded smem row stride (floats): 20*4=80B, 16B-aligned, conflict-free

// ---------------- scratch ----------------
__device__ float d_topk_w[MAXPOS];
__device__ int   d_topk_idx[MAXPOS];
__device__ int   d_counts[NEXP];
__device__ int   d_offsets[NEXP];
__device__ int   d_cursor[NEXP];
__device__ int   d_perm[MAXPOS];
__device__ int   d_posmap[MAXPOS];
__device__ float d_act[(size_t)MAXPOS * IDIM];
__device__ float d_part[(size_t)MAXPOS * HDIM];

// ---------------- PTX helpers ----------------
__device__ __forceinline__ uint32_t f2tf(float f) {
    uint32_t u; asm("cvt.rna.tf32.f32 %0, %1;" : "=r"(u) : "f"(f)); return u;
}
__device__ __forceinline__ void cp16(uint32_t dst, const void* src, int sz) {
    asm volatile("cp.async.cg.shared.global [%0], [%1], 16, %2;\n"
                 :: "r"(dst), "l"(src), "r"(sz));
}
__device__ __forceinline__ void cp_commit() { asm volatile("cp.async.commit_group;\n"); }
template <int N>
__device__ __forceinline__ void cp_wait() { asm volatile("cp.async.wait_group %0;\n" :: "n"(N)); }

__device__ __forceinline__ void mma8(float* d, const uint32_t* a, uint32_t b0, uint32_t b1) {
    asm volatile(
        "mma.sync.aligned.m16n8k8.row.col.f32.tf32.tf32.f32 "
        "{%0,%1,%2,%3},{%4,%5,%6,%7},{%8,%9},{%0,%1,%2,%3};"
        : "+f"(d[0]), "+f"(d[1]), "+f"(d[2]), "+f"(d[3])
        : "r"(a[0]), "r"(a[1]), "r"(a[2]), "r"(a[3]), "r"(b0), "r"(b1));
}

// ---------------- kernel 0: zero counters ----------------
__global__ void zero_counts_kernel() {
    if (threadIdx.x < NEXP) d_counts[threadIdx.x] = 0;
}

// ---------------- kernel 1: router ----------------
__global__ __launch_bounds__(256) void router_kernel(
    const float* __restrict__ x, const float* __restrict__ rw)
{
    __shared__ float xs[HDIM];
    __shared__ float logits[NEXP];
    const int t = blockIdx.x;
    const float* xrow = x + (size_t)t * HDIM;
    for (int j = threadIdx.x; j < HDIM; j += blockDim.x) xs[j] = xrow[j];
    __syncthreads();

    const int warp = threadIdx.x >> 5;
    const int lane = threadIdx.x & 31;
    for (int e = warp; e < NEXP; e += 8) {
        const float* w = rw + (size_t)e * HDIM;
        float s = 0.f;
        for (int j = lane; j < HDIM; j += 32) s = fmaf(xs[j], w[j], s);
        #pragma unroll
        for (int o = 16; o > 0; o >>= 1) s += __shfl_xor_sync(0xffffffffu, s, o);
        if (lane == 0) logits[e] = s;
    }
    __syncthreads();

    if (threadIdx.x == 0) {
        float vals[TOPK]; int idx[TOPK];
        bool used[NEXP];
        #pragma unroll
        for (int e = 0; e < NEXP; e++) used[e] = false;
        for (int k = 0; k < TOPK; k++) {
            float best = -1e30f; int bi = 0;
            for (int e = 0; e < NEXP; e++)
                if (!used[e] && logits[e] > best) { best = logits[e]; bi = e; }
            used[bi] = true; vals[k] = best; idx[k] = bi;
        }
        const float mx = vals[0];
        float sum = 0.f;
        #pragma unroll
        for (int k = 0; k < TOPK; k++) { vals[k] = expf(vals[k] - mx); sum += vals[k]; }
        const float inv = 1.f / sum;
        #pragma unroll
        for (int k = 0; k < TOPK; k++) {
            d_topk_w[t * TOPK + k]   = vals[k] * inv;
            d_topk_idx[t * TOPK + k] = idx[k];
            atomicAdd(&d_counts[idx[k]], 1);
        }
    }
}

// ---------------- kernel 2: exclusive scan ----------------
__global__ void scan_kernel() {
    int off = 0;
    for (int e = 0; e < NEXP; e++) {
        d_offsets[e] = off; d_cursor[e] = off; off += d_counts[e];
    }
}

// ---------------- kernel 3: per-expert token lists ----------------
__global__ void fill_kernel() {
    const int i = blockIdx.x * blockDim.x + threadIdx.x;
    if (i < MAXPOS) {
        const int e = d_topk_idx[i];
        const int pos = atomicAdd(&d_cursor[e], 1);
        d_perm[pos] = i / TOPK;
        d_posmap[i] = pos;
    }
}

// ---------------- kernel 4: fused gate/up tf32 GEMM + SiLU ----------------
// grid = (NEXP, IDIM/BN, T_TOK/BM), block = 256 (8 warps: 4M x 2N, 32x32 warp tiles)
__global__ __launch_bounds__(256) void gemm1_kernel(
    const float* __restrict__ x,
    const float* __restrict__ gw,
    const float* __restrict__ uw)
{
    const int e   = blockIdx.x;
    const int cnt = d_counts[e];
    const int m0  = blockIdx.z * BM;
    if (m0 >= cnt) return;
    const int n0  = blockIdx.y * BN;
    const int off = d_offsets[e];

    __shared__ float As [2][BM * SA];
    __shared__ float Bgs[2][BN * SA];
    __shared__ float Bus[2][BN * SA];

    const int tid = threadIdx.x;
    // A loader: two fixed rows per thread
    const int arow0 = tid >> 2, arow1 = 64 + (tid >> 2);
    const int kc    = (tid & 3) * 4;
    const int gm0 = m0 + arow0, gm1 = m0 + arow1;
    const int sz0 = (gm0 < cnt) ? 16 : 0;
    const int sz1 = (gm1 < cnt) ? 16 : 0;
    const float* aptr0 = x + (size_t)d_perm[min(off + gm0, MAXPOS - 1)] * HDIM + kc;
    const float* aptr1 = x + (size_t)d_perm[min(off + gm1, MAXPOS - 1)] * HDIM + kc;
    // B loader: one fixed row per thread (gate + up)
    const int brow = tid >> 2;
    const float* gptr = gw + ((size_t)e * IDIM + n0 + brow) * HDIM + kc;
    const float* uptr = uw + ((size_t)e * IDIM + n0 + brow) * HDIM + kc;

    const uint32_t sA  = (uint32_t)__cvta_generic_to_shared(&As[0][0]);
    const uint32_t sBg = (uint32_t)__cvta_generic_to_shared(&Bgs[0][0]);
    const uint32_t sBu = (uint32_t)__cvta_generic_to_shared(&Bus[0][0]);
    const uint32_t aoff0 = (arow0 * SA + kc) * 4, aoff1 = (arow1 * SA + kc) * 4;
    const uint32_t boff  = (brow * SA + kc) * 4;

    #define LOAD_STAGE1(st, k0)                                             \
        do {                                                                \
            cp16(sA  + (st) * BM * SA * 4 + aoff0, aptr0 + (k0), sz0);      \
            cp16(sA  + (st) * BM * SA * 4 + aoff1, aptr1 + (k0), sz1);      \
            cp16(sBg + (st) * BN * SA * 4 + boff,  gptr  + (k0), 16);       \
            cp16(sBu + (st) * BN * SA * 4 + boff,  uptr  + (k0), 16);       \
        } while (0)

    float accg[2][4][4] = {}, accu[2][4][4] = {};
    const int warp = tid >> 5, lane = tid & 31;
    const int wm = (warp >> 1) * 32, wn = (warp & 1) * 32;
    const int gid = lane >> 2, tig = lane & 3;

    LOAD_STAGE1(0, 0);
    cp_commit();

    const int KT = HDIM / BK;   // 128
    for (int kt = 0; kt < KT; kt++) {
        const int st = kt & 1;
        if (kt + 1 < KT) LOAD_STAGE1(st ^ 1, (kt + 1) * BK);
        cp_commit();
        cp_wait<1>();
        __syncthreads();

        const float* A  = As[st];
        const float* Bg = Bgs[st];
        const float* Bu = Bus[st];
        #pragma unroll
        for (int ks = 0; ks < 2; ks++) {
            const int kk = ks * 8;
            uint32_t af[2][4];
            #pragma unroll
            for (int mt = 0; mt < 2; mt++) {
                const int r = wm + mt * 16 + gid;
                af[mt][0] = f2tf(A[r * SA + kk + tig]);
                af[mt][1] = f2tf(A[(r + 8) * SA + kk + tig]);
                af[mt][2] = f2tf(A[r * SA + kk + tig + 4]);
                af[mt][3] = f2tf(A[(r + 8) * SA + kk + tig + 4]);
            }
            #pragma unroll
            for (int nt = 0; nt < 4; nt++) {
                const int n = wn + nt * 8 + gid;
                const uint32_t bg0 = f2tf(Bg[n * SA + kk + tig]);
                const uint32_t bg1 = f2tf(Bg[n * SA + kk + tig + 4]);
                const uint32_t bu0 = f2tf(Bu[n * SA + kk + tig]);
                const uint32_t bu1 = f2tf(Bu[n * SA + kk + tig + 4]);
                #pragma unroll
                for (int mt = 0; mt < 2; mt++) {
                    mma8(accg[mt][nt], af[mt], bg0, bg1);
                    mma8(accu[mt][nt], af[mt], bu0, bu1);
                }
            }
        }
        __syncthreads();
    }

    // epilogue: SiLU(gate) * up -> d_act
    #pragma unroll
    for (int mt = 0; mt < 2; mt++) {
        const int m_lo = m0 + wm + mt * 16 + gid;
        const int m_hi = m_lo + 8;
        #pragma unroll
        for (int nt = 0; nt < 4; nt++) {
            const int gn = n0 + wn + nt * 8 + tig * 2;
            if (m_lo < cnt) {
                const float g0 = accg[mt][nt][0], g1 = accg[mt][nt][1];
                const float v0 = g0 / (1.f + expf(-g0)) * accu[mt][nt][0];
                const float v1 = g1 / (1.f + expf(-g1)) * accu[mt][nt][1];
                *(float2*)(d_act + (size_t)(off + m_lo) * IDIM + gn) = make_float2(v0, v1);
            }
            if (m_hi < cnt) {
                const float g2 = accg[mt][nt][2], g3 = accg[mt][nt][3];
                const float v2 = g2 / (1.f + expf(-g2)) * accu[mt][nt][2];
                const float v3 = g3 / (1.f + expf(-g3)) * accu[mt][nt][3];
                *(float2*)(d_act + (size_t)(off + m_hi) * IDIM + gn) = make_float2(v2, v3);
            }
        }
    }
    #undef LOAD_STAGE1
}

// ---------------- kernel 5: down tf32 GEMM ----------------
// grid = (NEXP, HDIM/BN, T_TOK/BM), block = 256
__global__ __launch_bounds__(256) void gemm2_kernel(const float* __restrict__ dw)
{
    const int e   = blockIdx.x;
    const int cnt = d_counts[e];
    const int m0  = blockIdx.z * BM;
    if (m0 >= cnt) return;
    const int n0  = blockIdx.y * BN;
    const int off = d_offsets[e];

    __shared__ float As[2][BM * SA];
    __shared__ float Bs[2][BN * SA];

    const int tid = threadIdx.x;
    const int arow0 = tid >> 2, arow1 = 64 + (tid >> 2);
    const int kc    = (tid & 3) * 4;
    const int gm0 = m0 + arow0, gm1 = m0 + arow1;
    const int sz0 = (gm0 < cnt) ? 16 : 0;
    const int sz1 = (gm1 < cnt) ? 16 : 0;
    const float* aptr0 = d_act + (size_t)min(off + gm0, MAXPOS - 1) * IDIM + kc;
    const float* aptr1 = d_act + (size_t)min(off + gm1, MAXPOS - 1) * IDIM + kc;
    const int brow = tid >> 2;
    const float* bptr = dw + ((size_t)e * HDIM + n0 + brow) * IDIM + kc;

    const uint32_t sA = (uint32_t)__cvta_generic_to_shared(&As[0][0]);
    const uint32_t sB = (uint32_t)__cvta_generic_to_shared(&Bs[0][0]);
    const uint32_t aoff0 = (arow0 * SA + kc) * 4, aoff1 = (arow1 * SA + kc) * 4;
    const uint32_t boff  = (brow * SA + kc) * 4;

    #define LOAD_STAGE2(st, k0)                                            \
        do {                                                               \
            cp16(sA + (st) * BM * SA * 4 + aoff0, aptr0 + (k0), sz0);      \
            cp16(sA + (st) * BM * SA * 4 + aoff1, aptr1 + (k0), sz1);      \
            cp16(sB + (st) * BN * SA * 4 + boff,  bptr  + (k0), 16);       \
        } while (0)

    float acc[2][4][4] = {};
    const int warp = tid >> 5, lane = tid & 31;
    const int wm = (warp >> 1) * 32, wn = (warp & 1) * 32;
    const int gid = lane >> 2, tig = lane & 3;

    LOAD_STAGE2(0, 0);
    cp_commit();

    const int KT = IDIM / BK;   // 48
    for (int kt = 0; kt < KT; kt++) {
        const int st = kt & 1;
        if (kt + 1 < KT) LOAD_STAGE2(st ^ 1, (kt + 1) * BK);
        cp_commit();
        cp_wait<1>();
        __syncthreads();

        const float* A = As[st];
        const float* B = Bs[st];
        #pragma unroll
        for (int ks = 0; ks < 2; ks++) {
            const int kk = ks * 8;
            uint32_t af[2][4];
            #pragma unroll
            for (int mt = 0; mt < 2; mt++) {
                const int r = wm + mt * 16 + gid;
                af[mt][0] = f2tf(A[r * SA + kk + tig]);
                af[mt][1] = f2tf(A[(r + 8) * SA + kk + tig]);
                af[mt][2] = f2tf(A[r * SA + kk + tig + 4]);
                af[mt][3] = f2tf(A[(r + 8) * SA + kk + tig + 4]);
            }
            #pragma unroll
            for (int nt = 0; nt < 4; nt++) {
                const int n = wn + nt * 8 + gid;
                const uint32_t b0 = f2tf(B[n * SA + kk + tig]);
                const uint32_t b1 = f2tf(B[n * SA + kk + tig + 4]);
                #pragma unroll
                for (int mt = 0; mt < 2; mt++)
                    mma8(acc[mt][nt], af[mt], b0, b1);
            }
        }
        __syncthreads();
    }

    #pragma unroll
    for (int mt = 0; mt < 2; mt++) {
        const int m_lo = m0 + wm + mt * 16 + gid;
        const int m_hi = m_lo + 8;
        #pragma unroll
        for (int nt = 0; nt < 4; nt++) {
            const int gn = n0 + wn + nt * 8 + tig * 2;
            if (m_lo < cnt)
                *(float2*)(d_part + (size_t)(off + m_lo) * HDIM + gn) =
                    make_float2(acc[mt][nt][0], acc[mt][nt][1]);
            if (m_hi < cnt)
                *(float2*)(d_part + (size_t)(off + m_hi) * HDIM + gn) =
                    make_float2(acc[mt][nt][2], acc[mt][nt][3]);
        }
    }
    #undef LOAD_STAGE2
}

// ---------------- kernel 6: deterministic combine ----------------
__global__ __launch_bounds__(256) void combine_kernel(float* __restrict__ out)
{
    const int t = blockIdx.x;
    const int h = blockIdx.y * 256 + threadIdx.x;
    float w[TOPK]; int pos[TOPK];
    #pragma unroll
    for (int k = 0; k < TOPK; k++) {
        w[k]   = d_topk_w[t * TOPK + k];
        pos[k] = d_posmap[t * TOPK + k];
    }
    float s = 0.f;
    #pragma unroll
    for (int k = 0; k < TOPK; k++)
        s = fmaf(w[k], d_part[(size_t)pos[k] * HDIM + h], s);
    out[(size_t)t * HDIM + h] = s;
}

// ---------------- launch ----------------
extern "C" void kernel_launch(void* const* d_in, const int* in_sizes, int n_in,
                              void* d_out, int out_size)
{
    const float* x  = (const float*)d_in[0];
    const float* rw = (const float*)d_in[1];
    const float* gw = (const float*)d_in[2];
    const float* uw = (const float*)d_in[3];
    const float* dw = (const float*)d_in[4];
    float* out = (float*)d_out;

    zero_counts_kernel<<<1, 64>>>();
    router_kernel<<<T_TOK, 256>>>(x, rw);
    scan_kernel<<<1, 1>>>();
    fill_kernel<<<MAXPOS / 256, 256>>>();
    gemm1_kernel<<<dim3(NEXP, IDIM / BN, T_TOK / BM), 256>>>(x, gw, uw);
    gemm2_kernel<<<dim3(NEXP, HDIM / BN, T_TOK / BM), 256>>>(dw);
    combine_kernel<<<dim3(T_TOK, HDIM / 256), 256>>>(out);
}